// round 10
// baseline (speedup 1.0000x reference)
#include <cuda_runtime.h>
#include <cstdint>
#include <cstddef>

#define IMH 224
#define IMW 224
#define NB  32
#define NO  64
#define PLANE (IMH * IMW)
#define TPI   196                 // tiles per image: 28 row-tiles x 7 col-tiles
#define NTILES (NB * TPI)         // 6272 tiles of 8 rows x 32 cols
#define GRIDSZ (148 * 5)
#define PADT  44                  // raw-tile row pitch (44 % 32 = 12 -> conflict-free)
#define TELEM (12 * 36)           // halo tile elements

__device__ __forceinline__ float fsqrt_approx(float x) {
    float r; asm("sqrt.approx.f32 %0, %1;" : "=f"(r) : "f"(x)); return r;
}
__device__ __forceinline__ float f2tf32f(float v) {
    float u; asm("cvt.rna.tf32.f32 %0, %1;" : "=f"(u) : "f"(v)); return u;
}
__device__ __forceinline__ void mma_tf32(float& c0, float& c1, float& c2, float& c3,
                                         uint32_t a0, uint32_t a1, uint32_t a2, uint32_t a3,
                                         float b0f, float b1f) {
    asm volatile(
        "mma.sync.aligned.m16n8k8.row.col.f32.tf32.tf32.f32 "
        "{%0,%1,%2,%3}, {%4,%5,%6,%7}, {%8,%9}, {%0,%1,%2,%3};"
        : "+f"(c0), "+f"(c1), "+f"(c2), "+f"(c3)
        : "r"(a0), "r"(a1), "r"(a2), "r"(a3),
          "r"(__float_as_uint(b0f)), "r"(__float_as_uint(b1f)));
}

// ---------------------------------------------------------------------------
// Persistent tf32 mma.sync kernel, raw-tile, 5 CTAs/SM, fused epilogue.
// A fragments hold tf32(-2*w); accumulators are initialized to x2+w2, so
// after the K loop c = x2 + w2 - 2*x.w and the epilogue is sqrt(|c|) + STG.
// B fragments are fed as raw fp32 bits (HMMA.TF32 truncates mantissa in HW).
// CTA = 128 threads = 4 warps; tile = 8 pixel rows x 32 cols; warp w owns
// pixel rows {hh+w, hh+w+4}; nh outer so only half the B frags are live.
// ---------------------------------------------------------------------------
__global__ __launch_bounds__(128, 5)
void conv_dist_mma(const float* __restrict__ x,
                   const float* __restrict__ wgt,
                   float* __restrict__ out) {
    __shared__ float sT[2][12 * PADT];                     // raw halo tiles
    __shared__ __align__(16) uint32_t sWf[16 * 32 * 4];    // [m][ks][lane][slot], -2w
    __shared__ __align__(8) float sX2[4][2][32];           // [warp][rt][pixel col]
    __shared__ float sW2[NO];

    const int tid  = threadIdx.x;
    const int wid  = tid >> 5;
    const int lane = tid & 31;
    const int g    = lane >> 2;
    const int tig  = lane & 3;

    // ---- one-time init: weight fragments (scaled by -2) + w2 ----
    for (int idx = tid; idx < 2048; idx += 128) {
        const int slot = idx & 3;
        const int ln   = (idx >> 2) & 31;
        const int ks   = (idx >> 7) & 3;
        const int m    = idx >> 9;
        const int row  = m * 16 + (ln >> 2) + ((slot & 1) ? 8 : 0);
        const int col  = ks * 8 + (ln & 3) + ((slot & 2) ? 4 : 0);
        const float v  = (col < 25) ? -2.f * wgt[row * 25 + col] : 0.f;
        sWf[idx] = __float_as_uint(f2tf32f(v));
    }
    if (tid < NO) {
        const float* wr = wgt + tid * 25;
        float s = 0.f;
#pragma unroll
        for (int t = 0; t < 25; t++) s = fmaf(wr[t], wr[t], s);
        sW2[tid] = s;
    }

    // per-thread tap offsets within raw tile: q=0..6, k=4q+tig (clamped to 24)
    uint32_t off[7];
#pragma unroll
    for (int q = 0; q < 7; q++) {
        int k = 4 * q + tig; if (k > 24) k = 24;
        off[q] = (uint32_t)((k / 5) * PADT + (k % 5));
    }
    // SMEM store offsets for halo tile load (idx fixed per thread)
    uint32_t soff[4];
#pragma unroll
    for (int r = 0; r < 4; r++) {
        const int idx = tid + 128 * r;
        soff[r] = (idx < TELEM) ? (uint32_t)((idx / 36) * PADT + (idx % 36)) : 0u;
    }
    __syncthreads();

    // ---- prologue: prefetch first halo tile into regs ----
    int tI = blockIdx.x;
    float pv[4];
    {
        const int b = tI / TPI, r2 = tI % TPI;
        const int hh = (r2 / 7) * 8, ww = (r2 % 7) * 32;
        const float* xb = x + (size_t)b * PLANE;
#pragma unroll
        for (int r = 0; r < 4; r++) {
            const int idx = tid + 128 * r;
            float v = 0.f;
            if (idx < TELEM) {
                const int trow = idx / 36, tcol = idx % 36;
                const int h = hh - 2 + trow, w = ww - 2 + tcol;
                if ((unsigned)h < IMH && (unsigned)w < IMW)
                    v = __ldg(xb + h * IMW + w);
            }
            pv[r] = v;
        }
    }

    int buf = 0;
    for (; tI < NTILES; tI += gridDim.x, buf ^= 1) {
        const int b = tI / TPI, r2 = tI % TPI;
        const int hh = (r2 / 7) * 8, ww = (r2 % 7) * 32;

        // ---- store prefetched tile ----
#pragma unroll
        for (int r = 0; r < 4; r++)
            if (tid + 128 * r < TELEM) sT[buf][soff[r]] = pv[r];
        __syncthreads();

        // ---- prefetch NEXT tile (hidden behind GEMM) ----
        const int nI = tI + gridDim.x;
        if (nI < NTILES) {
            const int nb = nI / TPI, nr2 = nI % TPI;
            const int nhh = (nr2 / 7) * 8, nww = (nr2 % 7) * 32;
            const float* xb = x + (size_t)nb * PLANE;
#pragma unroll
            for (int r = 0; r < 4; r++) {
                const int idx = tid + 128 * r;
                float v = 0.f;
                if (idx < TELEM) {
                    const int trow = idx / 36, tcol = idx % 36;
                    const int h = nhh - 2 + trow, w = nww - 2 + tcol;
                    if ((unsigned)h < IMH && (unsigned)w < IMW)
                        v = __ldg(xb + h * IMW + w);
                }
                pv[r] = v;
            }
        }

        const size_t obase = (size_t)b * NO * PLANE + (size_t)(hh + wid) * IMW + ww;
        const float* tb0 = &sT[buf][(wid) * PADT + g];
        const float* tb1 = &sT[buf][(wid + 4) * PADT + g];

        // ---- process pixel-column halves: nt = 2*nh + nt2 ----
#pragma unroll
        for (int nh = 0; nh < 2; nh++) {
            // B fragments for this half (raw fp32; HMMA truncates to tf32)
            float bfv[4][2][2][2];   // [ks][rt][nt2][b]
#pragma unroll
            for (int ks = 0; ks < 4; ks++) {
#pragma unroll
                for (int rt = 0; rt < 2; rt++) {
                    const float* tb = rt ? tb1 : tb0;
#pragma unroll
                    for (int nt2 = 0; nt2 < 2; nt2++) {
                        const int nt = 2 * nh + nt2;
                        float b0, b1;
                        if (ks < 3) {
                            b0 = tb[off[2 * ks] + nt * 8];
                            b1 = tb[off[2 * ks + 1] + nt * 8];
                        } else {
                            b0 = (tig == 0) ? tb[off[6] + nt * 8] : 0.f;
                            b1 = 0.f;
                        }
                        bfv[ks][rt][nt2][0] = b0;
                        bfv[ks][rt][nt2][1] = b1;
                    }
                }
            }

            // x2 for these pixels from the raw fragments
#pragma unroll
            for (int rt = 0; rt < 2; rt++) {
#pragma unroll
                for (int nt2 = 0; nt2 < 2; nt2++) {
                    float s = 0.f;
#pragma unroll
                    for (int ks = 0; ks < 4; ks++) {
                        s = fmaf(bfv[ks][rt][nt2][0], bfv[ks][rt][nt2][0], s);
                        s = fmaf(bfv[ks][rt][nt2][1], bfv[ks][rt][nt2][1], s);
                    }
                    s += __shfl_xor_sync(0xffffffffu, s, 1);
                    s += __shfl_xor_sync(0xffffffffu, s, 2);
                    if (tig == 0) sX2[wid][rt][(2 * nh + nt2) * 8 + g] = s;
                }
            }
            __syncwarp();

            float2 xp[2][2];
#pragma unroll
            for (int rt = 0; rt < 2; rt++)
#pragma unroll
                for (int nt2 = 0; nt2 < 2; nt2++)
                    xp[rt][nt2] = *(const float2*)
                        &sX2[wid][rt][(2 * nh + nt2) * 8 + 2 * tig];

            // ---- 4 m-passes over channels ----
#pragma unroll
            for (int m = 0; m < 4; m++) {
                uint4 af[4];
#pragma unroll
                for (int ks = 0; ks < 4; ks++)
                    af[ks] = *(const uint4*)&sWf[((m * 4 + ks) * 32 + lane) * 4];

                const int ch0 = m * 16 + g;
                const float w20 = sW2[ch0];
                const float w21 = sW2[ch0 + 8];

                // accumulators pre-loaded with x2 + w2
                float c[2][2][4];
#pragma unroll
                for (int rt = 0; rt < 2; rt++)
#pragma unroll
                    for (int nt2 = 0; nt2 < 2; nt2++) {
                        c[rt][nt2][0] = xp[rt][nt2].x + w20;
                        c[rt][nt2][1] = xp[rt][nt2].y + w20;
                        c[rt][nt2][2] = xp[rt][nt2].x + w21;
                        c[rt][nt2][3] = xp[rt][nt2].y + w21;
                    }

#pragma unroll
                for (int ks = 0; ks < 4; ks++)
#pragma unroll
                    for (int rt = 0; rt < 2; rt++)
#pragma unroll
                        for (int nt2 = 0; nt2 < 2; nt2++)
                            mma_tf32(c[rt][nt2][0], c[rt][nt2][1],
                                     c[rt][nt2][2], c[rt][nt2][3],
                                     af[ks].x, af[ks].y, af[ks].z, af[ks].w,
                                     bfv[ks][rt][nt2][0], bfv[ks][rt][nt2][1]);

                float* o0 = out + obase + (size_t)ch0 * PLANE;
                float* o1 = o0 + (size_t)8 * PLANE;

#pragma unroll
                for (int rt = 0; rt < 2; rt++) {
#pragma unroll
                    for (int nt2 = 0; nt2 < 2; nt2++) {
                        const int nt = 2 * nh + nt2;
                        const int pc = nt * 8 + 2 * tig + rt * 4 * IMW;
                        float2 r0v, r1v;
                        r0v.x = fsqrt_approx(fabsf(c[rt][nt2][0]));
                        r0v.y = fsqrt_approx(fabsf(c[rt][nt2][1]));
                        r1v.x = fsqrt_approx(fabsf(c[rt][nt2][2]));
                        r1v.y = fsqrt_approx(fabsf(c[rt][nt2][3]));
                        *(float2*)(o0 + pc) = r0v;
                        *(float2*)(o1 + pc) = r1v;
                    }
                }
            }
        }
    }
}

extern "C" void kernel_launch(void* const* d_in, const int* in_sizes, int n_in,
                              void* d_out, int out_size) {
    (void)in_sizes; (void)n_in; (void)out_size;
    const float* x = (const float*)d_in[0];
    const float* w = (const float*)d_in[1];
    float* out = (float*)d_out;
    conv_dist_mma<<<GRIDSZ, 128>>>(x, w, out);
}